// round 14
// baseline (speedup 1.0000x reference)
#include <cuda_runtime.h>
#include <cuda_fp16.h>
#include <math.h>

#define N_IMG 2
#define C_IN 48
#define H 192
#define W 192
#define HW (H*W)          // 36864
#define NHW (N_IMG*HW)    // 73728
#define DIM 128
#define PE_DIM 48
#define SCALE 0.25f
#define TWO_PI 6.283185307179586f
#define EPS_F 1e-6f

#define WT_LD 56          // padded row length (halves) for Wt / As
#define CS_LD 136         // padded C-staging row (halves)
#define GEMM_SMEM (14336 + 34816 + 512)   // As + union(Ws,Cs) + bias = 49664

// scratch
__device__ __half g_kv[(size_t)NHW * 256];  // [p][256]: 0:128 = k, 128:256 = v (fp16)
__device__ __half g_q [(size_t)NHW * 128];  // [p][128] (fp16, pre-scaled by SCALE)
__device__ int    g_x0[NHW];
__device__ float  g_off4[4 * NHW];          // conv partial sums per channel slab
__device__ float  g_pbk[4 * DIM];           // pb @ k_w  (no bias)
__device__ float  g_pbv[4 * DIM];           // pb @ v_w
__device__ __half g_wt[3][DIM * WT_LD];     // transposed fp16 weights Wt[o][c]
__device__ float  g_bs[3][DIM];             // biases (q pre-scaled)

__constant__ float c_inv_dt[12] = {
    1.0f, 0.46415888336127786f, 0.21544346900318834f, 0.1f,
    0.046415888336127774f, 0.021544346900318832f, 0.01f,
    0.0046415888336127786f, 0.0021544346900318834f, 0.001f,
    0.00046415888336127786f, 0.00021544346900318834f
};

__device__ __forceinline__ void mma16816(float* c, const unsigned* a, const unsigned* b) {
    asm volatile(
        "mma.sync.aligned.m16n8k16.row.col.f32.f16.f16.f32 "
        "{%0,%1,%2,%3}, {%4,%5,%6,%7}, {%8,%9}, {%0,%1,%2,%3};"
        : "+f"(c[0]), "+f"(c[1]), "+f"(c[2]), "+f"(c[3])
        : "r"(a[0]), "r"(a[1]), "r"(a[2]), "r"(a[3]), "r"(b[0]), "r"(b[1]));
}

// ---------------------------------------------------------------------------
// K0: weight prep (blocks 0-2) + window-position-bias (blocks 3-6)
// ---------------------------------------------------------------------------
__global__ void wtpb_kernel(const float* __restrict__ qw, const float* __restrict__ qb,
                            const float* __restrict__ kw, const float* __restrict__ kb,
                            const float* __restrict__ vw, const float* __restrict__ vb) {
    int b = blockIdx.x;
    int o = threadIdx.x;  // 0..127
    if (b < 3) {
        int mat = b;
        const float* Wm = (mat == 0) ? kw : (mat == 1) ? vw : qw;
        const float* bm = (mat == 0) ? kb : (mat == 1) ? vb : qb;
        float sc = (mat == 2) ? SCALE : 1.0f;
        #pragma unroll
        for (int c = 0; c < 48; c++)
            g_wt[mat][o * WT_LD + c] = __float2half(Wm[c * DIM + o] * sc);
        #pragma unroll
        for (int c = 48; c < WT_LD; c++)
            g_wt[mat][o * WT_LD + c] = __float2half(0.0f);
        g_bs[mat][o] = bm[o] * sc;
    } else {
        int j = b - 3;  // 0..3
        float dy = (float)(j >> 1);
        float dx = (float)(j & 1);
        float yv_ = dy / (1.0f + EPS_F) * TWO_PI;
        float xv_ = dx / (1.0f + EPS_F) * TWO_PI;
        float acck = 0.0f, accv = 0.0f;
        #pragma unroll
        for (int m = 0; m < 12; m++) {
            float sy, cy, sx, cx;
            __sincosf(yv_ * c_inv_dt[m], &sy, &cy);
            __sincosf(xv_ * c_inv_dt[m], &sx, &cx);
            acck += sy * kw[(2*m)*DIM + o]    + cy * kw[(2*m+1)*DIM + o]
                  + sx * kw[(24+2*m)*DIM + o] + cx * kw[(25+2*m)*DIM + o];
            accv += sy * vw[(2*m)*DIM + o]    + cy * vw[(2*m+1)*DIM + o]
                  + sx * vw[(24+2*m)*DIM + o] + cx * vw[(25+2*m)*DIM + o];
        }
        g_pbk[j*DIM + o] = acck;
        g_pbv[j*DIM + o] = accv;
    }
}

// ---------------------------------------------------------------------------
// MMA core shared by kv/q gemm paths. 512 threads = 16 warps, warp 32x32.
// ---------------------------------------------------------------------------
__device__ __forceinline__ void gemm_core(
        char* dynsmem, int tid, int mat, __half* C, int ld, int obase) {
    __half (*As)[WT_LD] = (__half(*)[WT_LD])dynsmem;
    __half (*Ws)[WT_LD] = (__half(*)[WT_LD])(dynsmem + 14336);
    __half (*Cs)[CS_LD] = (__half(*)[CS_LD])(dynsmem + 14336);
    float* sbias = (float*)(dynsmem + 14336 + 34816);

    // load weight tile + bias into union buffer
    {
        const uint2* src = (const uint2*)g_wt[mat];
        uint2* dst = (uint2*)&Ws[0][0];
        #pragma unroll
        for (int kk = 0; kk < 4; kk++) {
            int idx = tid + kk * 512;
            if (idx < 1792) dst[idx] = src[idx];
        }
        if (tid < 128) sbias[tid] = g_bs[mat][tid];
    }
    __syncthreads();

    int wid = tid >> 5, lane = tid & 31;
    int m0 = (wid & 3) * 32;
    int n0 = (wid >> 2) * 32;
    int qr = lane >> 2;
    int qc = 2 * (lane & 3);

    float acc[2][4][4];
    #pragma unroll
    for (int mm = 0; mm < 2; mm++)
        #pragma unroll
        for (int nb = 0; nb < 4; nb++)
            #pragma unroll
            for (int e = 0; e < 4; e++) acc[mm][nb][e] = 0.0f;

    #pragma unroll
    for (int k16 = 0; k16 < 3; k16++) {
        int kc = k16 * 16 + qc;
        unsigned afr[2][4];
        #pragma unroll
        for (int mm = 0; mm < 2; mm++) {
            int row = m0 + mm * 16 + qr;
            afr[mm][0] = *(const unsigned*)&As[row][kc];
            afr[mm][1] = *(const unsigned*)&As[row + 8][kc];
            afr[mm][2] = *(const unsigned*)&As[row][kc + 8];
            afr[mm][3] = *(const unsigned*)&As[row + 8][kc + 8];
        }
        #pragma unroll
        for (int nb = 0; nb < 4; nb++) {
            int o = n0 + nb * 8 + qr;
            unsigned bfr[2];
            bfr[0] = *(const unsigned*)&Ws[o][kc];
            bfr[1] = *(const unsigned*)&Ws[o][kc + 8];
            mma16816(acc[0][nb], afr[0], bfr);
            mma16816(acc[1][nb], afr[1], bfr);
        }
    }
    __syncthreads();   // all warps done reading Ws before Cs overwrites it

    // epilogue: bias + fp16 into Cs
    #pragma unroll
    for (int mm = 0; mm < 2; mm++) {
        #pragma unroll
        for (int nb = 0; nb < 4; nb++) {
            int col = n0 + nb * 8 + qc;
            float b0 = sbias[col], b1 = sbias[col + 1];
            int r0 = m0 + mm * 16 + qr;
            *(__half2*)&Cs[r0][col]     = __floats2half2_rn(acc[mm][nb][0] + b0, acc[mm][nb][1] + b1);
            *(__half2*)&Cs[r0 + 8][col] = __floats2half2_rn(acc[mm][nb][2] + b0, acc[mm][nb][3] + b1);
        }
    }
    __syncthreads();

    // coalesced store
    #pragma unroll
    for (int it = 0; it < 4; it++) {
        int idx = tid + it * 512;
        int row = idx >> 4;
        int c16 = (idx & 15) * 8;
        uint4 vv = *(const uint4*)&Cs[row][c16];
        *(uint4*)&C[(size_t)row * ld + obase + c16] = vv;
    }
    __syncthreads();   // before next pass overwrites Cs/Ws
}

// ---------------------------------------------------------------------------
// K1: combined kernel. Blocks [0,576): kv gemm (A=y, 2 weight passes).
//     Blocks [576,1152): conv partial slabs (32x16 px, 24 channels).
// ---------------------------------------------------------------------------
__global__ void __launch_bounds__(512, 2) kvconv_kernel(
        const float* __restrict__ y, const float* __restrict__ x,
        const float* __restrict__ cw) {
    extern __shared__ char dynsmem[];
    int tid = threadIdx.x;

    if (blockIdx.x < 576) {
        // ---------------- kv gemm ----------------
        __half (*As)[WT_LD] = (__half(*)[WT_LD])dynsmem;
        int p0 = blockIdx.x * 128;
        int n = p0 / HW;
        int hw0 = p0 - n * HW;
        {
            int i = tid & 127;
            int sel = tid >> 7;           // 0..3
            int cbase = sel * 12;
            const float* src = y + (size_t)n * C_IN * HW + hw0 + i;
            #pragma unroll
            for (int cc = 0; cc < 6; cc++) {
                int c = cbase + cc * 2;
                float f0 = src[(size_t)c * HW];
                float f1 = src[(size_t)(c + 1) * HW];
                *(__half2*)&As[i][c] = __floats2half2_rn(f0, f1);
            }
        }
        __syncthreads();
        __half* C = g_kv + (size_t)p0 * 256;
        gemm_core(dynsmem, tid, 0, C, 256, 0);
        gemm_core(dynsmem, tid, 1, C, 256, 128);
    } else {
        // ---------------- conv slab ----------------
        float* sw = (float*)dynsmem;                       // 216 floats
        float (*tile)[34] = (float(*)[34])(dynsmem + 880); // 18x34 floats
        int cbi = blockIdx.x - 576;
        int bxc = cbi % 6;
        int t2 = cbi / 6;
        int byc = t2 % 12;
        int bz = t2 / 12;           // 0..7
        int slab = bz & 3, n = bz >> 2;
        int tx = tid & 31, ty = tid >> 5;   // 32 x 16

        if (tid < 216) sw[tid] = cw[slab * 216 + tid];

        int w0base = bxc * 32;
        int h0base = byc * 16;
        const float* src_base = ((slab < 2) ? y : x)
            + (size_t)n * C_IN * HW + (size_t)((slab & 1) * 24) * HW;

        float acc = 0.0f;
        __syncthreads();

        #pragma unroll 1
        for (int ic = 0; ic < 24; ic++) {
            const float* src = src_base + (size_t)ic * HW;
            #pragma unroll
            for (int idx = tid; idx < 612; idx += 512) {
                int r = idx / 34, cc = idx - r * 34;
                int hh = h0base + r - 1;
                int ww = w0base + cc - 1;
                float v = 0.0f;
                if (hh >= 0 && hh < H && ww >= 0 && ww < W) v = src[hh * W + ww];
                tile[r][cc] = v;
            }
            __syncthreads();
            const float* wr = &sw[ic * 9];
            #pragma unroll
            for (int kh = 0; kh < 3; kh++) {
                float t0 = tile[ty + kh][tx];
                float t1 = tile[ty + kh][tx + 1];
                float t2v = tile[ty + kh][tx + 2];
                acc += t0 * wr[kh * 3] + t1 * wr[kh * 3 + 1] + t2v * wr[kh * 3 + 2];
            }
            __syncthreads();
        }
        int p = n * HW + (h0base + ty) * W + w0base + tx;
        g_off4[slab * NHW + p] = acc;
    }
}

// ---------------------------------------------------------------------------
// K2: q gemm with inline offset finalize (sum slabs -> x0 + PE, no g_pe).
// ---------------------------------------------------------------------------
__global__ void __launch_bounds__(512, 2) gemmq_kernel(
        const float* __restrict__ x, const float* __restrict__ cb) {
    extern __shared__ char dynsmem[];
    __half (*As)[WT_LD] = (__half(*)[WT_LD])dynsmem;
    int tid = threadIdx.x;
    int p0 = blockIdx.x * 128;
    int n = p0 / HW;
    int hw0 = p0 - n * HW;

    {
        int i = tid & 127;
        int sel = tid >> 7;           // 0..3
        int cbase = sel * 12;
        const float* src = x + (size_t)n * C_IN * HW + hw0 + i;
        int p = p0 + i;
        if (sel < 2) {
            #pragma unroll
            for (int cc = 0; cc < 6; cc++) {
                int c = cbase + cc * 2;
                float f0 = src[(size_t)c * HW] + (float)(c & 1);
                float f1 = src[(size_t)(c + 1) * HW] + (float)((c + 1) & 1);
                *(__half2*)&As[i][c] = __floats2half2_rn(f0, f1);
            }
        } else {
            // inline finalize for this pixel
            float s01 = g_off4[p] + g_off4[NHW + p];
            float s23 = g_off4[2 * NHW + p] + g_off4[3 * NHW + p];
            float offv = (s01 + s23 + cb[0]) * (2.0f / (float)W);
            int hw = hw0 + i;
            int w0 = hw % W;
            float gx = (float)w0 + offv;
            float fl = floorf(gx);
            if (sel == 2) g_x0[p] = (int)fl;
            float xe = (gx - fl) * (TWO_PI / (2.0f + EPS_F));
            int mbase = (sel - 2) * 6;    // 0 or 6
            #pragma unroll
            for (int mm = 0; mm < 6; mm++) {
                float s, c;
                __sincosf(xe * c_inv_dt[mbase + mm], &s, &c);
                int ch = 24 + 2 * (mbase + mm);
                float f0 = src[(size_t)ch * HW] + s;
                float f1 = src[(size_t)(ch + 1) * HW] + c;
                *(__half2*)&As[i][ch] = __floats2half2_rn(f0, f1);
            }
        }
    }
    __syncthreads();
    gemm_core(dynsmem, tid, 2, g_q + (size_t)p0 * 128, 128, 0);
}

// ---------------------------------------------------------------------------
// K3: warp-per-pixel attention, lane owns 4 consecutive channels.
// ---------------------------------------------------------------------------
typedef unsigned long long ull;
__global__ void __launch_bounds__(512) attn_kernel(float* __restrict__ out) {
    __shared__ float spbk[4][128];
    __shared__ float spbv[4][128];
    __shared__ float sout[128][17];

    int tid = threadIdx.x;
    spbk[tid >> 7][tid & 127] = g_pbk[tid];
    spbv[tid >> 7][tid & 127] = g_pbv[tid];
    __syncthreads();

    int w = tid >> 5;
    int lane = tid & 31;
    int p = blockIdx.x * 16 + w;
    int n = p / HW;
    int hw = p - n * HW;
    int gh = hw / W;
    int x0 = g_x0[p];

    int lin[4];
    #pragma unroll
    for (int j = 0; j < 4; j++) {
        int iy = min(max(gh + (j >> 1), 0), H - 1);
        int ix = min(max(x0 + (j & 1),  0), W - 1);
        lin[j] = n * HW + iy * W + ix;
    }

    int c0 = lane * 4;

    float4 q4;
    {
        ull qq = *(const ull*)&g_q[(size_t)p * 128 + c0];
        float2 f0 = __half22float2(((const __half2*)&qq)[0]);
        float2 f1 = __half22float2(((const __half2*)&qq)[1]);
        q4 = make_float4(f0.x, f0.y, f1.x, f1.y);
    }

    float s[4];
    float4 v4[4];
    #pragma unroll
    for (int j = 0; j < 4; j++) {
        const __half* r = g_kv + (size_t)lin[j] * 256;
        ull kk = *(const ull*)&r[c0];
        ull vv = *(const ull*)&r[128 + c0];
        float2 k0 = __half22float2(((const __half2*)&kk)[0]);
        float2 k1 = __half22float2(((const __half2*)&kk)[1]);
        float2 w0 = __half22float2(((const __half2*)&vv)[0]);
        float2 w1 = __half22float2(((const __half2*)&vv)[1]);
        float4 pk = *(const float4*)&spbk[j][c0];
        float4 pv = *(const float4*)&spbv[j][c0];
        v4[j].x = w0.x + pv.x; v4[j].y = w0.y + pv.y;
        v4[j].z = w1.x + pv.z; v4[j].w = w1.y + pv.w;
        float part = q4.x * (k0.x + pk.x) + q4.y * (k0.y + pk.y)
                   + q4.z * (k1.x + pk.z) + q4.w * (k1.y + pk.w);
        part += __shfl_xor_sync(0xffffffffu, part, 1);
        part += __shfl_xor_sync(0xffffffffu, part, 2);
        s[j] = part;
    }

    float mx = fmaxf(fmaxf(s[0], s[1]), fmaxf(s[2], s[3]));
    float e0 = __expf(s[0] - mx), e1 = __expf(s[1] - mx);
    float e2 = __expf(s[2] - mx), e3 = __expf(s[3] - mx);
    float inv = 1.0f / (e0 + e1 + e2 + e3);
    float a0 = e0 * inv, a1 = e1 * inv, a2 = e2 * inv, a3 = e3 * inv;

    sout[c0 + 0][w] = a0 * v4[0].x + a1 * v4[1].x + a2 * v4[2].x + a3 * v4[3].x;
    sout[c0 + 1][w] = a0 * v4[0].y + a1 * v4[1].y + a2 * v4[2].y + a3 * v4[3].y;
    sout[c0 + 2][w] = a0 * v4[0].z + a1 * v4[1].z + a2 * v4[2].z + a3 * v4[3].z;
    sout[c0 + 3][w] = a0 * v4[0].w + a1 * v4[1].w + a2 * v4[2].w + a3 * v4[3].w;
    __syncthreads();

    int p0 = blockIdx.x * 16;
    int n0 = p0 / HW;
    int hw0 = p0 - n0 * HW;
    int ch = tid >> 2;
    int px = (tid & 3) * 4;
    float4 v = make_float4(sout[ch][px], sout[ch][px + 1], sout[ch][px + 2], sout[ch][px + 3]);
    *(float4*)&out[(size_t)n0 * DIM * HW + (size_t)ch * HW + hw0 + px] = v;
}

// ---------------------------------------------------------------------------
extern "C" void kernel_launch(void* const* d_in, const int* in_sizes, int n_in,
                              void* d_out, int out_size) {
    const float* y      = (const float*)d_in[0];
    const float* x      = (const float*)d_in[1];
    const float* conv_w = (const float*)d_in[2];
    const float* conv_b = (const float*)d_in[3];
    const float* q_w    = (const float*)d_in[4];
    const float* q_b    = (const float*)d_in[5];
    const float* k_w    = (const float*)d_in[6];
    const float* k_b    = (const float*)d_in[7];
    const float* v_w    = (const float*)d_in[8];
    const float* v_b    = (const float*)d_in[9];
    float* out = (float*)d_out;

    cudaFuncSetAttribute(kvconv_kernel,
                         cudaFuncAttributeMaxDynamicSharedMemorySize, GEMM_SMEM);
    cudaFuncSetAttribute(gemmq_kernel,
                         cudaFuncAttributeMaxDynamicSharedMemorySize, GEMM_SMEM);

    wtpb_kernel<<<7, 128>>>(q_w, q_b, k_w, k_b, v_w, v_b);

    kvconv_kernel<<<1152, 512, GEMM_SMEM>>>(y, x, conv_w);

    gemmq_kernel<<<576, 512, GEMM_SMEM>>>(x, conv_b);

    attn_kernel<<<NHW / 16, 512>>>(out);
}

// round 17
// speedup vs baseline: 1.3455x; 1.3455x over previous
#include <cuda_runtime.h>
#include <cuda_fp16.h>
#include <math.h>

#define N_IMG 2
#define C_IN 48
#define H 192
#define W 192
#define HW (H*W)          // 36864
#define NHW (N_IMG*HW)    // 73728
#define DIM 128
#define PE_DIM 48
#define SCALE 0.25f
#define TWO_PI 6.283185307179586f
#define EPS_F 1e-6f

#define WT_LD 56          // padded row length (halves) for Wt / As
#define CS_LD 136         // padded C-staging row (halves)
#define GEMM_SMEM (14336 + 34816 + 512)   // As + union(Ws,Cs) + bias = 49664

// scratch
__device__ __half g_kv[(size_t)NHW * 256];  // [p][256]: 0:128 = k, 128:256 = v (fp16)
__device__ __half g_q [(size_t)NHW * 128];  // [p][128] (fp16, pre-scaled by SCALE)
__device__ int    g_x0[NHW];
__device__ float  g_off4[4 * NHW];          // conv partial sums per channel slab
__device__ float  g_pbk[4 * DIM];           // pb @ k_w  (no bias)
__device__ float  g_pbv[4 * DIM];           // pb @ v_w
__device__ __half g_wt[3][DIM * WT_LD];     // transposed fp16 weights Wt[o][c]
__device__ float  g_bs[3][DIM];             // biases (q pre-scaled)

__constant__ float c_inv_dt[12] = {
    1.0f, 0.46415888336127786f, 0.21544346900318834f, 0.1f,
    0.046415888336127774f, 0.021544346900318832f, 0.01f,
    0.0046415888336127786f, 0.0021544346900318834f, 0.001f,
    0.00046415888336127786f, 0.00021544346900318834f
};

__device__ __forceinline__ void mma16816(float* c, const unsigned* a, const unsigned* b) {
    asm volatile(
        "mma.sync.aligned.m16n8k16.row.col.f32.f16.f16.f32 "
        "{%0,%1,%2,%3}, {%4,%5,%6,%7}, {%8,%9}, {%0,%1,%2,%3};"
        : "+f"(c[0]), "+f"(c[1]), "+f"(c[2]), "+f"(c[3])
        : "r"(a[0]), "r"(a[1]), "r"(a[2]), "r"(a[3]), "r"(b[0]), "r"(b[1]));
}

// ---------------------------------------------------------------------------
// L1: prep kernel. Blocks [0,1152): conv partial slabs (32x8 px, 24 channels).
//     Blocks [1152,1155): weight transpose+fp16. Blocks [1155,1159): window pb.
// 256 threads, small static smem -> full occupancy for the conv part.
// ---------------------------------------------------------------------------
__global__ void __launch_bounds__(256) prep_kernel(
        const float* __restrict__ y, const float* __restrict__ x,
        const float* __restrict__ cw,
        const float* __restrict__ qw, const float* __restrict__ qb,
        const float* __restrict__ kw, const float* __restrict__ kb,
        const float* __restrict__ vw, const float* __restrict__ vb) {
    __shared__ float sw[24 * 9];
    __shared__ float tile[10][34];

    int tid = threadIdx.x;
    int b = blockIdx.x;

    if (b < 1152) {
        // ---------------- conv slab ----------------
        int bxc = b % 6;
        int t2 = b / 6;
        int byc = t2 % 24;
        int bz = t2 / 24;            // 0..7
        int slab = bz & 3, n = bz >> 2;
        int tx = tid & 31, ty = tid >> 5;   // 32 x 8

        if (tid < 216) sw[tid] = cw[slab * 216 + tid];

        int w0base = bxc * 32;
        int h0base = byc * 8;
        const float* src_base = ((slab < 2) ? y : x)
            + (size_t)n * C_IN * HW + (size_t)((slab & 1) * 24) * HW;

        float acc = 0.0f;
        __syncthreads();

        #pragma unroll 1
        for (int ic = 0; ic < 24; ic++) {
            const float* src = src_base + (size_t)ic * HW;
            #pragma unroll
            for (int idx = tid; idx < 340; idx += 256) {
                int r = idx / 34, cc = idx - r * 34;
                int hh = h0base + r - 1;
                int ww = w0base + cc - 1;
                float v = 0.0f;
                if (hh >= 0 && hh < H && ww >= 0 && ww < W) v = src[hh * W + ww];
                tile[r][cc] = v;
            }
            __syncthreads();
            const float* wr = &sw[ic * 9];
            #pragma unroll
            for (int kh = 0; kh < 3; kh++) {
                float t0 = tile[ty + kh][tx];
                float t1 = tile[ty + kh][tx + 1];
                float t2v = tile[ty + kh][tx + 2];
                acc += t0 * wr[kh * 3] + t1 * wr[kh * 3 + 1] + t2v * wr[kh * 3 + 2];
            }
            __syncthreads();
        }
        int p = n * HW + (h0base + ty) * W + w0base + tx;
        g_off4[slab * NHW + p] = acc;
    } else if (b < 1155) {
        // ---------------- weight prep ----------------
        if (tid < 128) {
            int mat = b - 1152;
            int o = tid;
            const float* Wm = (mat == 0) ? kw : (mat == 1) ? vw : qw;
            const float* bm = (mat == 0) ? kb : (mat == 1) ? vb : qb;
            float sc = (mat == 2) ? SCALE : 1.0f;
            #pragma unroll
            for (int c = 0; c < 48; c++)
                g_wt[mat][o * WT_LD + c] = __float2half(Wm[c * DIM + o] * sc);
            #pragma unroll
            for (int c = 48; c < WT_LD; c++)
                g_wt[mat][o * WT_LD + c] = __float2half(0.0f);
            g_bs[mat][o] = bm[o] * sc;
        }
    } else {
        // ---------------- window position bias ----------------
        if (tid < 128) {
            int j = b - 1155;  // 0..3
            int o = tid;
            float dy = (float)(j >> 1);
            float dx = (float)(j & 1);
            float yv_ = dy / (1.0f + EPS_F) * TWO_PI;
            float xv_ = dx / (1.0f + EPS_F) * TWO_PI;
            float acck = 0.0f, accv = 0.0f;
            #pragma unroll
            for (int m = 0; m < 12; m++) {
                float sy, cy, sx, cx;
                __sincosf(yv_ * c_inv_dt[m], &sy, &cy);
                __sincosf(xv_ * c_inv_dt[m], &sx, &cx);
                acck += sy * kw[(2*m)*DIM + o]    + cy * kw[(2*m+1)*DIM + o]
                      + sx * kw[(24+2*m)*DIM + o] + cx * kw[(25+2*m)*DIM + o];
                accv += sy * vw[(2*m)*DIM + o]    + cy * vw[(2*m+1)*DIM + o]
                      + sx * vw[(24+2*m)*DIM + o] + cx * vw[(25+2*m)*DIM + o];
            }
            g_pbk[j*DIM + o] = acck;
            g_pbv[j*DIM + o] = accv;
        }
    }
}

// ---------------------------------------------------------------------------
// MMA core: 512 threads = 16 warps, warp 32x32, K=48, one weight matrix.
// ---------------------------------------------------------------------------
__device__ __forceinline__ void gemm_core(
        char* dynsmem, int tid, int mat, __half* C, int ld, int obase) {
    __half (*As)[WT_LD] = (__half(*)[WT_LD])dynsmem;
    __half (*Ws)[WT_LD] = (__half(*)[WT_LD])(dynsmem + 14336);
    __half (*Cs)[CS_LD] = (__half(*)[CS_LD])(dynsmem + 14336);
    float* sbias = (float*)(dynsmem + 14336 + 34816);

    // load weight tile + bias into union buffer
    {
        const uint2* src = (const uint2*)g_wt[mat];
        uint2* dst = (uint2*)&Ws[0][0];
        #pragma unroll
        for (int kk = 0; kk < 4; kk++) {
            int idx = tid + kk * 512;
            if (idx < 1792) dst[idx] = src[idx];
        }
        if (tid < 128) sbias[tid] = g_bs[mat][tid];
    }
    __syncthreads();

    int wid = tid >> 5, lane = tid & 31;
    int m0 = (wid & 3) * 32;
    int n0 = (wid >> 2) * 32;
    int qr = lane >> 2;
    int qc = 2 * (lane & 3);

    float acc[2][4][4];
    #pragma unroll
    for (int mm = 0; mm < 2; mm++)
        #pragma unroll
        for (int nb = 0; nb < 4; nb++)
            #pragma unroll
            for (int e = 0; e < 4; e++) acc[mm][nb][e] = 0.0f;

    #pragma unroll
    for (int k16 = 0; k16 < 3; k16++) {
        int kc = k16 * 16 + qc;
        unsigned afr[2][4];
        #pragma unroll
        for (int mm = 0; mm < 2; mm++) {
            int row = m0 + mm * 16 + qr;
            afr[mm][0] = *(const unsigned*)&As[row][kc];
            afr[mm][1] = *(const unsigned*)&As[row + 8][kc];
            afr[mm][2] = *(const unsigned*)&As[row][kc + 8];
            afr[mm][3] = *(const unsigned*)&As[row + 8][kc + 8];
        }
        #pragma unroll
        for (int nb = 0; nb < 4; nb++) {
            int o = n0 + nb * 8 + qr;
            unsigned bfr[2];
            bfr[0] = *(const unsigned*)&Ws[o][kc];
            bfr[1] = *(const unsigned*)&Ws[o][kc + 8];
            mma16816(acc[0][nb], afr[0], bfr);
            mma16816(acc[1][nb], afr[1], bfr);
        }
    }
    __syncthreads();   // all warps done reading Ws before Cs overwrites it

    // epilogue: bias + fp16 into Cs
    #pragma unroll
    for (int mm = 0; mm < 2; mm++) {
        #pragma unroll
        for (int nb = 0; nb < 4; nb++) {
            int col = n0 + nb * 8 + qc;
            float b0 = sbias[col], b1 = sbias[col + 1];
            int r0 = m0 + mm * 16 + qr;
            *(__half2*)&Cs[r0][col]     = __floats2half2_rn(acc[mm][nb][0] + b0, acc[mm][nb][1] + b1);
            *(__half2*)&Cs[r0 + 8][col] = __floats2half2_rn(acc[mm][nb][2] + b0, acc[mm][nb][3] + b1);
        }
    }
    __syncthreads();

    // coalesced store
    #pragma unroll
    for (int it = 0; it < 4; it++) {
        int idx = tid + it * 512;
        int row = idx >> 4;
        int c16 = (idx & 15) * 8;
        uint4 vv = *(const uint4*)&Cs[row][c16];
        *(uint4*)&C[(size_t)row * ld + obase + c16] = vv;
    }
}

// ---------------------------------------------------------------------------
// L2: gemm launch, grid (576, 3). by = 0: k (A=y), 1: v (A=y),
//     2: q (A=x+PE, inline offset finalize -> g_x0). Single pass each.
// ---------------------------------------------------------------------------
__global__ void __launch_bounds__(512, 2) gemm_kernel(
        const float* __restrict__ y, const float* __restrict__ x,
        const float* __restrict__ cb) {
    extern __shared__ char dynsmem[];
    __half (*As)[WT_LD] = (__half(*)[WT_LD])dynsmem;
    int tid = threadIdx.x;
    int mat = blockIdx.y;           // 0=k, 1=v, 2=q
    int p0 = blockIdx.x * 128;
    int n = p0 / HW;
    int hw0 = p0 - n * HW;

    {
        int i = tid & 127;
        int sel = tid >> 7;           // 0..3
        int cbase = sel * 12;
        const float* src = ((mat < 2) ? y : x) + (size_t)n * C_IN * HW + hw0 + i;
        if (mat < 2) {
            #pragma unroll
            for (int cc = 0; cc < 6; cc++) {
                int c = cbase + cc * 2;
                float f0 = src[(size_t)c * HW];
                float f1 = src[(size_t)(c + 1) * HW];
                *(__half2*)&As[i][c] = __floats2half2_rn(f0, f1);
            }
        } else {
            int p = p0 + i;
            if (sel < 2) {
                #pragma unroll
                for (int cc = 0; cc < 6; cc++) {
                    int c = cbase + cc * 2;
                    float f0 = src[(size_t)c * HW] + (float)(c & 1);
                    float f1 = src[(size_t)(c + 1) * HW] + (float)((c + 1) & 1);
                    *(__half2*)&As[i][c] = __floats2half2_rn(f0, f1);
                }
            } else {
                // inline offset finalize for this pixel
                float s01 = g_off4[p] + g_off4[NHW + p];
                float s23 = g_off4[2 * NHW + p] + g_off4[3 * NHW + p];
                float offv = (s01 + s23 + cb[0]) * (2.0f / (float)W);
                int hw = hw0 + i;
                int w0 = hw % W;
                float gx = (float)w0 + offv;
                float fl = floorf(gx);
                if (sel == 2) g_x0[p] = (int)fl;
                float xe = (gx - fl) * (TWO_PI / (2.0f + EPS_F));
                int mbase = (sel - 2) * 6;    // 0 or 6
                #pragma unroll
                for (int mm = 0; mm < 6; mm++) {
                    float s, c;
                    __sincosf(xe * c_inv_dt[mbase + mm], &s, &c);
                    int ch = 24 + 2 * (mbase + mm);
                    float f0 = src[(size_t)ch * HW] + s;
                    float f1 = src[(size_t)(ch + 1) * HW] + c;
                    *(__half2*)&As[i][ch] = __floats2half2_rn(f0, f1);
                }
            }
        }
    }
    __syncthreads();

    if (mat == 2)      gemm_core(dynsmem, tid, 2, g_q + (size_t)p0 * 128, 128, 0);
    else if (mat == 0) gemm_core(dynsmem, tid, 0, g_kv + (size_t)p0 * 256, 256, 0);
    else               gemm_core(dynsmem, tid, 1, g_kv + (size_t)p0 * 256, 256, 128);
}

// ---------------------------------------------------------------------------
// L3: warp-per-pixel attention, lane owns 4 consecutive channels.
// ---------------------------------------------------------------------------
typedef unsigned long long ull;
__global__ void __launch_bounds__(512) attn_kernel(float* __restrict__ out) {
    __shared__ float spbk[4][128];
    __shared__ float spbv[4][128];
    __shared__ float sout[128][17];

    int tid = threadIdx.x;
    spbk[tid >> 7][tid & 127] = g_pbk[tid];
    spbv[tid >> 7][tid & 127] = g_pbv[tid];
    __syncthreads();

    int w = tid >> 5;
    int lane = tid & 31;
    int p = blockIdx.x * 16 + w;
    int n = p / HW;
    int hw = p - n * HW;
    int gh = hw / W;
    int x0 = g_x0[p];

    int lin[4];
    #pragma unroll
    for (int j = 0; j < 4; j++) {
        int iy = min(max(gh + (j >> 1), 0), H - 1);
        int ix = min(max(x0 + (j & 1),  0), W - 1);
        lin[j] = n * HW + iy * W + ix;
    }

    int c0 = lane * 4;

    float4 q4;
    {
        ull qq = *(const ull*)&g_q[(size_t)p * 128 + c0];
        float2 f0 = __half22float2(((const __half2*)&qq)[0]);
        float2 f1 = __half22float2(((const __half2*)&qq)[1]);
        q4 = make_float4(f0.x, f0.y, f1.x, f1.y);
    }

    float s[4];
    float4 v4[4];
    #pragma unroll
    for (int j = 0; j < 4; j++) {
        const __half* r = g_kv + (size_t)lin[j] * 256;
        ull kk = *(const ull*)&r[c0];
        ull vv = *(const ull*)&r[128 + c0];
        float2 k0 = __half22float2(((const __half2*)&kk)[0]);
        float2 k1 = __half22float2(((const __half2*)&kk)[1]);
        float2 w0 = __half22float2(((const __half2*)&vv)[0]);
        float2 w1 = __half22float2(((const __half2*)&vv)[1]);
        float4 pk = *(const float4*)&spbk[j][c0];
        float4 pv = *(const float4*)&spbv[j][c0];
        v4[j].x = w0.x + pv.x; v4[j].y = w0.y + pv.y;
        v4[j].z = w1.x + pv.z; v4[j].w = w1.y + pv.w;
        float part = q4.x * (k0.x + pk.x) + q4.y * (k0.y + pk.y)
                   + q4.z * (k1.x + pk.z) + q4.w * (k1.y + pk.w);
        part += __shfl_xor_sync(0xffffffffu, part, 1);
        part += __shfl_xor_sync(0xffffffffu, part, 2);
        s[j] = part;
    }

    float mx = fmaxf(fmaxf(s[0], s[1]), fmaxf(s[2], s[3]));
    float e0 = __expf(s[0] - mx), e1 = __expf(s[1] - mx);
    float e2 = __expf(s[2] - mx), e3 = __expf(s[3] - mx);
    float inv = 1.0f / (e0 + e1 + e2 + e3);
    float a0 = e0 * inv, a1 = e1 * inv, a2 = e2 * inv, a3 = e3 * inv;

    sout[c0 + 0][w] = a0 * v4[0].x + a1 * v4[1].x + a2 * v4[2].x + a3 * v4[3].x;
    sout[c0 + 1][w] = a0 * v4[0].y + a1 * v4[1].y + a2 * v4[2].y + a3 * v4[3].y;
    sout[c0 + 2][w] = a0 * v4[0].z + a1 * v4[1].z + a2 * v4[2].z + a3 * v4[3].z;
    sout[c0 + 3][w] = a0 * v4[0].w + a1 * v4[1].w + a2 * v4[2].w + a3 * v4[3].w;
    __syncthreads();

    int p0 = blockIdx.x * 16;
    int n0 = p0 / HW;
    int hw0 = p0 - n0 * HW;
    int ch = tid >> 2;
    int px = (tid & 3) * 4;
    float4 v = make_float4(sout[ch][px], sout[ch][px + 1], sout[ch][px + 2], sout[ch][px + 3]);
    *(float4*)&out[(size_t)n0 * DIM * HW + (size_t)ch * HW + hw0 + px] = v;
}

// ---------------------------------------------------------------------------
extern "C" void kernel_launch(void* const* d_in, const int* in_sizes, int n_in,
                              void* d_out, int out_size) {
    const float* y      = (const float*)d_in[0];
    const float* x      = (const float*)d_in[1];
    const float* conv_w = (const float*)d_in[2];
    const float* conv_b = (const float*)d_in[3];
    const float* q_w    = (const float*)d_in[4];
    const float* q_b    = (const float*)d_in[5];
    const float* k_w    = (const float*)d_in[6];
    const float* k_b    = (const float*)d_in[7];
    const float* v_w    = (const float*)d_in[8];
    const float* v_b    = (const float*)d_in[9];
    float* out = (float*)d_out;

    cudaFuncSetAttribute(gemm_kernel,
                         cudaFuncAttributeMaxDynamicSharedMemorySize, GEMM_SMEM);

    prep_kernel<<<1159, 256>>>(y, x, conv_w, q_w, q_b, k_w, k_b, v_w, v_b);

    dim3 ggrid(576, 3);
    gemm_kernel<<<ggrid, 512, GEMM_SMEM>>>(y, x, conv_b);

    attn_kernel<<<NHW / 16, 512>>>(out);
}